// round 2
// baseline (speedup 1.0000x reference)
#include <cuda_runtime.h>
#include <cstdint>

// Problem dims (fixed by the reference).
#define M_DIM 2048
#define N_DIM 8192
#define K_DIM 8192
#define NGROUPS ((N_DIM * K_DIM) / 8)   // 8388608 groups of 8 outputs

// Device-global scratch (no cudaMalloc allowed).
__device__ float g_w[(size_t)N_DIM * K_DIM];   // dequantized, tf32-rounded weights (N,K) row-major
__device__ float g_x[(size_t)M_DIM * K_DIM];   // tf32-rounded activations

__device__ __forceinline__ float to_tf32(float f) {
    float r;
    asm("cvt.rna.tf32.f32 %0, %1;" : "=f"(r) : "f"(f));
    return r;
}

// ---------------------------------------------------------------------------
// Prep: round x to tf32 once so the GEMM mainloop does zero CVT work.
// ---------------------------------------------------------------------------
__global__ void __launch_bounds__(256) xprep_kernel(const float* __restrict__ x) {
    size_t i = ((size_t)blockIdx.x * 256 + threadIdx.x) * 4;
    float4 v = *reinterpret_cast<const float4*>(x + i);
    v.x = to_tf32(v.x);
    v.y = to_tf32(v.y);
    v.z = to_tf32(v.z);
    v.w = to_tf32(v.w);
    *reinterpret_cast<float4*>(g_x + i) = v;
}

// ---------------------------------------------------------------------------
// Dequant: each thread handles one 3-byte group -> 8 3-bit indices -> 8 floats.
// Flat block order == row-major (N, K), so output is written contiguously.
// 16 consecutive threads share one codebook block (L1-friendly gathers).
// ---------------------------------------------------------------------------
__global__ void __launch_bounds__(256) dequant_kernel(const int* __restrict__ packed,
                                                      const float* __restrict__ codebook) {
    int g = blockIdx.x * 256 + threadIdx.x;           // group id, < NGROUPS
    int p0 = packed[3 * g + 0];
    int p1 = packed[3 * g + 1];
    int p2 = packed[3 * g + 2];
    unsigned bits = (unsigned)(p0 & 255) | ((unsigned)(p1 & 255) << 8) |
                    ((unsigned)(p2 & 255) << 16);
    const float* cb = codebook + ((size_t)(g >> 4)) * 8;  // 128 elems / 8 per group = 16 groups/block
    float v[8];
#pragma unroll
    for (int j = 0; j < 8; j++) {
        v[j] = to_tf32(__ldg(cb + ((bits >> (3 * j)) & 7)));
    }
    float4* out = reinterpret_cast<float4*>(g_w + (size_t)g * 8);
    out[0] = make_float4(v[0], v[1], v[2], v[3]);
    out[1] = make_float4(v[4], v[5], v[6], v[7]);
}

// ---------------------------------------------------------------------------
// GEMM: y[m,n] = sum_k x[m,k] * w[n,k]   (TN: both operands K-major)
// Tile: BM=BN=128, BK=32, 256 threads (8 warps, 2x4 warp grid, 64x32 warp tile)
// mma.sync.m16n8k8 tf32, fp32 accum. Double-buffered cp.async pipeline.
// ---------------------------------------------------------------------------
#define BM 128
#define BN 128
#define BK 32
#define LDS_STRIDE 36            // BK + 4 floats pad: conflict-free frag reads, 16B-aligned rows
#define K_TILES (K_DIM / BK)     // 256

__device__ __forceinline__ void cp_async16(float* s, const float* g) {
    unsigned sa = (unsigned)__cvta_generic_to_shared(s);
    asm volatile("cp.async.cg.shared.global [%0], [%1], 16;\n" ::"r"(sa), "l"(g));
}

__device__ __forceinline__ void mma_tf32(float* c, const unsigned* a, const unsigned* b) {
    asm volatile(
        "mma.sync.aligned.m16n8k8.row.col.f32.tf32.tf32.f32 "
        "{%0,%1,%2,%3}, {%4,%5,%6,%7}, {%8,%9}, {%0,%1,%2,%3};\n"
        : "+f"(c[0]), "+f"(c[1]), "+f"(c[2]), "+f"(c[3])
        : "r"(a[0]), "r"(a[1]), "r"(a[2]), "r"(a[3]), "r"(b[0]), "r"(b[1]));
}

__global__ void __launch_bounds__(256) gemm_kernel(float* __restrict__ y) {
    extern __shared__ float smem[];
    float* As = smem;                              // [2][BM][LDS_STRIDE]
    float* Bs = smem + 2 * BM * LDS_STRIDE;        // [2][BN][LDS_STRIDE]

    const int tid = threadIdx.x;
    const int wid = tid >> 5;
    const int lane = tid & 31;
    const int wm = wid >> 2;        // 0..1  (64-row warp tile)
    const int wn = wid & 3;         // 0..3  (32-col warp tile)
    const int gr = lane >> 2;       // group id within warp (0..7)
    const int tg = lane & 3;        // thread-in-group (0..3)

    const int m0 = blockIdx.y * BM;
    const int n0 = blockIdx.x * BN;
    const float* Ag = g_x + (size_t)m0 * K_DIM;
    const float* Bg = g_w + (size_t)n0 * K_DIM;

    float acc[4][4][4];
#pragma unroll
    for (int i = 0; i < 4; i++)
#pragma unroll
        for (int j = 0; j < 4; j++)
#pragma unroll
            for (int r = 0; r < 4; r++) acc[i][j][r] = 0.0f;

    // ---- tile loader: 128x32 floats each for A and B, 4 float4 per thread each ----
    auto load_tile = [&](int kt, int buf) {
        const float* a = Ag + kt * BK;
        const float* b = Bg + kt * BK;
        float* as = As + buf * BM * LDS_STRIDE;
        float* bs = Bs + buf * BN * LDS_STRIDE;
#pragma unroll
        for (int i = 0; i < 4; i++) {
            int f = tid + i * 256;          // 0..1023 float4 slots
            int row = f >> 3;               // 8 float4 per 32-float row
            int c4 = (f & 7) * 4;
            cp_async16(as + row * LDS_STRIDE + c4, a + (size_t)row * K_DIM + c4);
            cp_async16(bs + row * LDS_STRIDE + c4, b + (size_t)row * K_DIM + c4);
        }
    };

    auto compute = [&](int buf) {
        const float* as = As + buf * BM * LDS_STRIDE + (wm * 64) * LDS_STRIDE;
        const float* bs = Bs + buf * BN * LDS_STRIDE + (wn * 32) * LDS_STRIDE;
#pragma unroll
        for (int ks = 0; ks < 4; ks++) {
            const int kb = ks * 8;
            unsigned a[4][4], b[4][2];
#pragma unroll
            for (int i = 0; i < 4; i++) {
                const float* p = as + (i * 16 + gr) * LDS_STRIDE + kb + tg;
                a[i][0] = __float_as_uint(p[0]);
                a[i][2] = __float_as_uint(p[4]);
                const float* p2 = p + 8 * LDS_STRIDE;
                a[i][1] = __float_as_uint(p2[0]);
                a[i][3] = __float_as_uint(p2[4]);
            }
#pragma unroll
            for (int j = 0; j < 4; j++) {
                const float* p = bs + (j * 8 + gr) * LDS_STRIDE + kb + tg;
                b[j][0] = __float_as_uint(p[0]);
                b[j][1] = __float_as_uint(p[4]);
            }
#pragma unroll
            for (int i = 0; i < 4; i++)
#pragma unroll
                for (int j = 0; j < 4; j++) mma_tf32(acc[i][j], a[i], b[j]);
        }
    };

    // ---- pipelined mainloop ----
    load_tile(0, 0);
    asm volatile("cp.async.commit_group;\n");
    asm volatile("cp.async.wait_group 0;\n");
    __syncthreads();

    int buf = 0;
#pragma unroll 1
    for (int kt = 0; kt < K_TILES; kt++) {
        if (kt + 1 < K_TILES) {
            load_tile(kt + 1, buf ^ 1);
            asm volatile("cp.async.commit_group;\n");
        }
        compute(buf);
        if (kt + 1 < K_TILES) {
            asm volatile("cp.async.wait_group 0;\n");
            __syncthreads();
        }
        buf ^= 1;
    }

    // ---- epilogue: fp32 accumulators straight to gmem ----
#pragma unroll
    for (int i = 0; i < 4; i++) {
#pragma unroll
        for (int j = 0; j < 4; j++) {
            int row = m0 + wm * 64 + i * 16 + gr;
            int col = n0 + wn * 32 + j * 8 + tg * 2;
            *reinterpret_cast<float2*>(y + (size_t)row * N_DIM + col) =
                make_float2(acc[i][j][0], acc[i][j][1]);
            *reinterpret_cast<float2*>(y + (size_t)(row + 8) * N_DIM + col) =
                make_float2(acc[i][j][2], acc[i][j][3]);
        }
    }
}

// ---------------------------------------------------------------------------
// Launch
// ---------------------------------------------------------------------------
extern "C" void kernel_launch(void* const* d_in, const int* in_sizes, int n_in,
                              void* d_out, int out_size) {
    // Identify inputs by element count (robust to ordering).
    const float* x = nullptr;
    const int* packed = nullptr;
    const float* codebook = nullptr;
    for (int i = 0; i < n_in; i++) {
        if (in_sizes[i] == M_DIM * K_DIM) x = (const float*)d_in[i];
        else if (in_sizes[i] == NGROUPS * 3) packed = (const int*)d_in[i];
        else codebook = (const float*)d_in[i];
    }
    float* y = (float*)d_out;

    xprep_kernel<<<(M_DIM * (size_t)K_DIM) / (256 * 4), 256>>>(x);
    dequant_kernel<<<NGROUPS / 256, 256>>>(packed, codebook);

    const int smem_bytes = 2 * (BM + BN) * LDS_STRIDE * (int)sizeof(float);  // 73728
    cudaFuncSetAttribute(gemm_kernel, cudaFuncAttributeMaxDynamicSharedMemorySize, smem_bytes);
    dim3 grid(N_DIM / BN, M_DIM / BM);  // (64, 16)
    gemm_kernel<<<grid, 256, smem_bytes>>>(y);
}

// round 7
// speedup vs baseline: 1.9474x; 1.9474x over previous
#include <cuda_runtime.h>
#include <cuda_fp16.h>
#include <cstdint>

// ---------------------------------------------------------------------------
// Problem dims
// ---------------------------------------------------------------------------
#define M_DIM 2048
#define N_DIM 8192
#define K_DIM 8192
#define NGROUPS ((N_DIM * K_DIM) / 8)   // 8388608

// Device-global scratch (no cudaMalloc allowed) — fp16 operands
__device__ __align__(256) __half g_w[(size_t)N_DIM * K_DIM];   // (N,K) row-major
__device__ __align__(256) __half g_x[(size_t)M_DIM * K_DIM];

// ---------------------------------------------------------------------------
// Prep: fp32 -> fp16, 8 elems/thread
// ---------------------------------------------------------------------------
__global__ void __launch_bounds__(256) xprep_kernel(const float* __restrict__ x) {
    size_t i = ((size_t)blockIdx.x * 256 + threadIdx.x) * 8;
    float4 v0 = *reinterpret_cast<const float4*>(x + i);
    float4 v1 = *reinterpret_cast<const float4*>(x + i + 4);
    union { __half2 h[4]; uint4 u; } o;
    o.h[0] = __floats2half2_rn(v0.x, v0.y);
    o.h[1] = __floats2half2_rn(v0.z, v0.w);
    o.h[2] = __floats2half2_rn(v1.x, v1.y);
    o.h[3] = __floats2half2_rn(v1.z, v1.w);
    *reinterpret_cast<uint4*>(g_x + i) = o.u;
}

// ---------------------------------------------------------------------------
// Dequant: one 3-byte group -> 8 3-bit indices -> 8 fp16 weights (16B store)
// ---------------------------------------------------------------------------
__global__ void __launch_bounds__(256) dequant_kernel(const int* __restrict__ packed,
                                                      const float* __restrict__ codebook) {
    int g = blockIdx.x * 256 + threadIdx.x;
    int p0 = packed[3 * g + 0];
    int p1 = packed[3 * g + 1];
    int p2 = packed[3 * g + 2];
    unsigned bits = (unsigned)(p0 & 255) | ((unsigned)(p1 & 255) << 8) |
                    ((unsigned)(p2 & 255) << 16);
    const float* cb = codebook + ((size_t)(g >> 4)) * 8;
    union { __half h[8]; uint4 u; } o;
#pragma unroll
    for (int j = 0; j < 8; j++)
        o.h[j] = __float2half_rn(__ldg(cb + ((bits >> (3 * j)) & 7)));
    *reinterpret_cast<uint4*>(g_w + (size_t)g * 8) = o.u;
}

// ---------------------------------------------------------------------------
// GEMM: y[m,n] = sum_k x[m,k] * w[n,k]   fp16 inputs, fp32 accumulate
// BM=BN=128, BK=64 halves, 256 threads (8 warps 2x4, warp tile 64x32)
// mma.sync.m16n8k16.f32.f16.f16.f32, double-buffered cp.async, 2 CTAs/SM.
// ---------------------------------------------------------------------------
#define BM 128
#define BN 128
#define BKH 64                        // k-halves per stage
#define SW 36                         // smem row stride in b32 words (64 halves + 8 pad)
#define K_TILES (K_DIM / BKH)         // 128

__device__ __forceinline__ void cp_async16(void* s, const void* g) {
    unsigned sa = (unsigned)__cvta_generic_to_shared(s);
    asm volatile("cp.async.cg.shared.global [%0], [%1], 16;\n" ::"r"(sa), "l"(g));
}

__device__ __forceinline__ void mma_f16(float* c, const unsigned* a, const unsigned* b) {
    asm volatile(
        "mma.sync.aligned.m16n8k16.row.col.f32.f16.f16.f32 "
        "{%0,%1,%2,%3}, {%4,%5,%6,%7}, {%8,%9}, {%0,%1,%2,%3};\n"
        : "+f"(c[0]), "+f"(c[1]), "+f"(c[2]), "+f"(c[3])
        : "r"(a[0]), "r"(a[1]), "r"(a[2]), "r"(a[3]), "r"(b[0]), "r"(b[1]));
}

__global__ void __launch_bounds__(256, 2) gemm_kernel(float* __restrict__ y) {
    extern __shared__ unsigned smem[];          // b32 words
    unsigned* As = smem;                        // [2][BM][SW]
    unsigned* Bs = smem + 2 * BM * SW;          // [2][BN][SW]

    const int tid = threadIdx.x;
    const int wid = tid >> 5;
    const int lane = tid & 31;
    const int wm = wid >> 2;        // 0..1
    const int wn = wid & 3;         // 0..3
    const int gr = lane >> 2;       // 0..7
    const int tg = lane & 3;        // 0..3

    const int m0 = blockIdx.x * BM;   // m-fastest rasterization: B panels L2-resident
    const int n0 = blockIdx.y * BN;
    const __half* Ag = g_x + (size_t)m0 * K_DIM;
    const __half* Bg = g_w + (size_t)n0 * K_DIM;

    float acc[4][4][4];
#pragma unroll
    for (int i = 0; i < 4; i++)
#pragma unroll
        for (int j = 0; j < 4; j++)
#pragma unroll
            for (int r = 0; r < 4; r++) acc[i][j][r] = 0.0f;

    // tile loader: 128 rows x 64 halves (128B) per matrix = 1024 16B chunks each
    auto load_tile = [&](int kt, int buf) {
        const __half* a = Ag + kt * BKH;
        const __half* b = Bg + kt * BKH;
        unsigned* as = As + buf * BM * SW;
        unsigned* bs = Bs + buf * BN * SW;
#pragma unroll
        for (int i = 0; i < 4; i++) {
            int f = tid + i * 256;            // 0..1023
            int row = f >> 3;                 // 8 chunks per row
            int ch = f & 7;
            cp_async16(as + row * SW + ch * 4, a + (size_t)row * K_DIM + ch * 8);
            cp_async16(bs + row * SW + ch * 4, b + (size_t)row * K_DIM + ch * 8);
        }
    };

    auto compute = [&](int buf) {
        const unsigned* as = As + buf * BM * SW + (wm * 64) * SW;
        const unsigned* bs = Bs + buf * BN * SW + (wn * 32) * SW;
#pragma unroll
        for (int ks = 0; ks < 4; ks++) {       // 4 x k16 steps per BK=64
            const int kw = ks * 8;             // word offset
            unsigned a[4][4], b[4][2];
#pragma unroll
            for (int i = 0; i < 4; i++) {
                const unsigned* p = as + (i * 16 + gr) * SW + kw + tg;
                a[i][0] = p[0];                // A[gr][2tg..]
                a[i][1] = p[8 * SW];           // A[gr+8][2tg..]
                a[i][2] = p[4];                // A[gr][2tg+8..]
                a[i][3] = p[8 * SW + 4];       // A[gr+8][2tg+8..]
            }
#pragma unroll
            for (int j = 0; j < 4; j++) {
                const unsigned* p = bs + (j * 8 + gr) * SW + kw + tg;
                b[j][0] = p[0];                // B[n=gr][2tg..]
                b[j][1] = p[4];                // B[n=gr][2tg+8..]
            }
#pragma unroll
            for (int i = 0; i < 4; i++)
#pragma unroll
                for (int j = 0; j < 4; j++) mma_f16(acc[i][j], a[i], b[j]);
        }
    };

    // pipelined mainloop (validated R1 control flow)
    load_tile(0, 0);
    asm volatile("cp.async.commit_group;\n");
    asm volatile("cp.async.wait_group 0;\n");
    __syncthreads();

    int buf = 0;
#pragma unroll 1
    for (int kt = 0; kt < K_TILES; kt++) {
        if (kt + 1 < K_TILES) {
            load_tile(kt + 1, buf ^ 1);
            asm volatile("cp.async.commit_group;\n");
        }
        compute(buf);
        if (kt + 1 < K_TILES) {
            asm volatile("cp.async.wait_group 0;\n");
            __syncthreads();
        }
        buf ^= 1;
    }

    // epilogue: fp32 accumulators straight to gmem
#pragma unroll
    for (int i = 0; i < 4; i++) {
#pragma unroll
        for (int j = 0; j < 4; j++) {
            int row = m0 + wm * 64 + i * 16 + gr;
            int col = n0 + wn * 32 + j * 8 + tg * 2;
            *reinterpret_cast<float2*>(y + (size_t)row * N_DIM + col) =
                make_float2(acc[i][j][0], acc[i][j][1]);
            *reinterpret_cast<float2*>(y + (size_t)(row + 8) * N_DIM + col) =
                make_float2(acc[i][j][2], acc[i][j][3]);
        }
    }
}

// ---------------------------------------------------------------------------
// Launch
// ---------------------------------------------------------------------------
extern "C" void kernel_launch(void* const* d_in, const int* in_sizes, int n_in,
                              void* d_out, int out_size) {
    const float* x = nullptr;
    const int* packed = nullptr;
    const float* codebook = nullptr;
    for (int i = 0; i < n_in; i++) {
        if (in_sizes[i] == M_DIM * K_DIM) x = (const float*)d_in[i];
        else if (in_sizes[i] == NGROUPS * 3) packed = (const int*)d_in[i];
        else codebook = (const float*)d_in[i];
    }
    float* y = (float*)d_out;

    xprep_kernel<<<(M_DIM * (size_t)K_DIM) / (256 * 8), 256>>>(x);
    dequant_kernel<<<NGROUPS / 256, 256>>>(packed, codebook);

    const int smem_bytes = 2 * (BM + BN) * SW * (int)sizeof(unsigned);  // 73728
    cudaFuncSetAttribute(gemm_kernel, cudaFuncAttributeMaxDynamicSharedMemorySize, smem_bytes);
    dim3 grid(M_DIM / BM, N_DIM / BN);   // (16, 64), m-fastest
    gemm_kernel<<<grid, 256, smem_bytes>>>(y);
}

// round 9
// speedup vs baseline: 2.1765x; 1.1177x over previous
#include <cuda_runtime.h>
#include <cuda_fp16.h>
#include <cstdint>

// ---------------------------------------------------------------------------
// Problem dims
// ---------------------------------------------------------------------------
#define M_DIM 2048
#define N_DIM 8192
#define K_DIM 8192
#define NGROUPS ((N_DIM * K_DIM) / 8)   // 8388608

// Device-global scratch (no cudaMalloc allowed) — fp16 operands
__device__ __align__(256) __half g_w[(size_t)N_DIM * K_DIM];   // (N,K) row-major
__device__ __align__(256) __half g_x[(size_t)M_DIM * K_DIM];

// ---------------------------------------------------------------------------
// Prep: fp32 -> fp16, 8 elems/thread
// ---------------------------------------------------------------------------
__global__ void __launch_bounds__(256) xprep_kernel(const float* __restrict__ x) {
    size_t i = ((size_t)blockIdx.x * 256 + threadIdx.x) * 8;
    float4 v0 = *reinterpret_cast<const float4*>(x + i);
    float4 v1 = *reinterpret_cast<const float4*>(x + i + 4);
    union { __half2 h[4]; uint4 u; } o;
    o.h[0] = __floats2half2_rn(v0.x, v0.y);
    o.h[1] = __floats2half2_rn(v0.z, v0.w);
    o.h[2] = __floats2half2_rn(v1.x, v1.y);
    o.h[3] = __floats2half2_rn(v1.z, v1.w);
    *reinterpret_cast<uint4*>(g_x + i) = o.u;
}

// ---------------------------------------------------------------------------
// Dequant: one 3-byte group -> 8 3-bit indices -> 8 fp16 weights (16B store)
// ---------------------------------------------------------------------------
__global__ void __launch_bounds__(256) dequant_kernel(const int* __restrict__ packed,
                                                      const float* __restrict__ codebook) {
    int g = blockIdx.x * 256 + threadIdx.x;
    int p0 = packed[3 * g + 0];
    int p1 = packed[3 * g + 1];
    int p2 = packed[3 * g + 2];
    unsigned bits = (unsigned)(p0 & 255) | ((unsigned)(p1 & 255) << 8) |
                    ((unsigned)(p2 & 255) << 16);
    const float* cb = codebook + ((size_t)(g >> 4)) * 8;
    union { __half h[8]; uint4 u; } o;
#pragma unroll
    for (int j = 0; j < 8; j++)
        o.h[j] = __float2half_rn(__ldg(cb + ((bits >> (3 * j)) & 7)));
    *reinterpret_cast<uint4*>(g_w + (size_t)g * 8) = o.u;
}

// ---------------------------------------------------------------------------
// GEMM: y[m,n] = sum_k x[m,k] * w[n,k]   fp16 inputs, fp32 accumulate
// BM=BN=128, BK=64 halves, 256 threads (8 warps 2x4, warp tile 64x32)
// mma.sync.m16n8k16 + ldmatrix.x4 fragment loads, double-buffered cp.async.
// ---------------------------------------------------------------------------
#define BM 128
#define BN 128
#define BKH 64                        // k-halves per stage
#define SW 36                         // smem row stride in b32 words (64 halves + 8 pad)
#define SWB (SW * 4)                  // row stride in bytes (144)
#define K_TILES (K_DIM / BKH)         // 128

__device__ __forceinline__ void cp_async16(void* s, const void* g) {
    unsigned sa = (unsigned)__cvta_generic_to_shared(s);
    asm volatile("cp.async.cg.shared.global [%0], [%1], 16;\n" ::"r"(sa), "l"(g));
}

__device__ __forceinline__ void ldsm_x4(unsigned& r0, unsigned& r1, unsigned& r2,
                                        unsigned& r3, uint32_t addr) {
    asm volatile("ldmatrix.sync.aligned.m8n8.x4.shared.b16 {%0,%1,%2,%3}, [%4];"
                 : "=r"(r0), "=r"(r1), "=r"(r2), "=r"(r3) : "r"(addr));
}

__device__ __forceinline__ void mma_f16(float* c, const unsigned* a, const unsigned* b) {
    asm volatile(
        "mma.sync.aligned.m16n8k16.row.col.f32.f16.f16.f32 "
        "{%0,%1,%2,%3}, {%4,%5,%6,%7}, {%8,%9}, {%0,%1,%2,%3};\n"
        : "+f"(c[0]), "+f"(c[1]), "+f"(c[2]), "+f"(c[3])
        : "r"(a[0]), "r"(a[1]), "r"(a[2]), "r"(a[3]), "r"(b[0]), "r"(b[1]));
}

__global__ void __launch_bounds__(256, 2) gemm_kernel(float* __restrict__ y) {
    extern __shared__ unsigned smem[];          // b32 words
    unsigned* As = smem;                        // [2][BM][SW]
    unsigned* Bs = smem + 2 * BM * SW;          // [2][BN][SW]
    const uint32_t smem_sa = (uint32_t)__cvta_generic_to_shared(smem);

    const int tid = threadIdx.x;
    const int wid = tid >> 5;
    const int lane = tid & 31;
    const int wm = wid >> 2;        // 0..1
    const int wn = wid & 3;         // 0..3
    const int gr = lane >> 2;       // 0..7
    const int tg = lane & 3;        // 0..3

    const int m0 = blockIdx.x * BM;   // m-fastest rasterization: B panels L2-resident
    const int n0 = blockIdx.y * BN;
    const __half* Ag = g_x + (size_t)m0 * K_DIM;
    const __half* Bg = g_w + (size_t)n0 * K_DIM;

    // ldmatrix per-lane base addresses (bytes, relative to buffer 0)
    // A: lanes 0-7 rows0-7/k0, 8-15 rows8-15/k0, 16-23 rows0-7/k8, 24-31 rows8-15/k8
    const uint32_t a_sa0 = smem_sa + (uint32_t)(wm * 64 + (lane & 15)) * SWB +
                           (uint32_t)(lane >> 4) * 16;
    // B: two j-tiles per x4: n=(lane&7)+(lane>>4)*8, koff=((lane>>3)&1)*8 halves
    const uint32_t b_sa0 = smem_sa + (uint32_t)(2 * BM * SW) * 4 +
                           (uint32_t)(wn * 32 + (lane & 7) + (lane >> 4) * 8) * SWB +
                           (uint32_t)((lane >> 3) & 1) * 16;

    float acc[4][4][4];
#pragma unroll
    for (int i = 0; i < 4; i++)
#pragma unroll
        for (int j = 0; j < 4; j++)
#pragma unroll
            for (int r = 0; r < 4; r++) acc[i][j][r] = 0.0f;

    // tile loader: 128 rows x 64 halves (128B) per matrix = 1024 16B chunks each
    auto load_tile = [&](int kt, int buf) {
        const __half* a = Ag + kt * BKH;
        const __half* b = Bg + kt * BKH;
        unsigned* as = As + buf * BM * SW;
        unsigned* bs = Bs + buf * BN * SW;
#pragma unroll
        for (int i = 0; i < 4; i++) {
            int f = tid + i * 256;            // 0..1023
            int row = f >> 3;                 // 8 chunks per row
            int ch = f & 7;
            cp_async16(as + row * SW + ch * 4, a + (size_t)row * K_DIM + ch * 8);
            cp_async16(bs + row * SW + ch * 4, b + (size_t)row * K_DIM + ch * 8);
        }
    };

    auto compute = [&](int buf) {
        const uint32_t abase = a_sa0 + (uint32_t)buf * BM * SW * 4;
        const uint32_t bbase = b_sa0 + (uint32_t)buf * BN * SW * 4;
#pragma unroll
        for (int ks = 0; ks < 4; ks++) {       // 4 x k16 steps per BK=64
            const uint32_t ko = (uint32_t)ks * 32;   // 8 words
            unsigned a[4][4], b[4][2];
#pragma unroll
            for (int i = 0; i < 4; i++)
                ldsm_x4(a[i][0], a[i][1], a[i][2], a[i][3],
                        abase + (uint32_t)i * 16 * SWB + ko);
#pragma unroll
            for (int jp = 0; jp < 2; jp++)
                ldsm_x4(b[2 * jp][0], b[2 * jp][1], b[2 * jp + 1][0], b[2 * jp + 1][1],
                        bbase + (uint32_t)jp * 16 * SWB + ko);
#pragma unroll
            for (int i = 0; i < 4; i++)
#pragma unroll
                for (int j = 0; j < 4; j++) mma_f16(acc[i][j], a[i], b[j]);
        }
    };

    // pipelined mainloop
    load_tile(0, 0);
    asm volatile("cp.async.commit_group;\n");
    asm volatile("cp.async.wait_group 0;\n");
    __syncthreads();

    int buf = 0;
#pragma unroll 1
    for (int kt = 0; kt < K_TILES; kt++) {
        if (kt + 1 < K_TILES) {
            load_tile(kt + 1, buf ^ 1);
            asm volatile("cp.async.commit_group;\n");
        }
        compute(buf);
        if (kt + 1 < K_TILES) {
            asm volatile("cp.async.wait_group 0;\n");
            __syncthreads();
        }
        buf ^= 1;
    }

    // epilogue: fp32 accumulators straight to gmem
#pragma unroll
    for (int i = 0; i < 4; i++) {
#pragma unroll
        for (int j = 0; j < 4; j++) {
            int row = m0 + wm * 64 + i * 16 + gr;
            int col = n0 + wn * 32 + j * 8 + tg * 2;
            *reinterpret_cast<float2*>(y + (size_t)row * N_DIM + col) =
                make_float2(acc[i][j][0], acc[i][j][1]);
            *reinterpret_cast<float2*>(y + (size_t)(row + 8) * N_DIM + col) =
                make_float2(acc[i][j][2], acc[i][j][3]);
        }
    }
}

// ---------------------------------------------------------------------------
// Launch
// ---------------------------------------------------------------------------
extern "C" void kernel_launch(void* const* d_in, const int* in_sizes, int n_in,
                              void* d_out, int out_size) {
    const float* x = nullptr;
    const int* packed = nullptr;
    const float* codebook = nullptr;
    for (int i = 0; i < n_in; i++) {
        if (in_sizes[i] == M_DIM * K_DIM) x = (const float*)d_in[i];
        else if (in_sizes[i] == NGROUPS * 3) packed = (const int*)d_in[i];
        else codebook = (const float*)d_in[i];
    }
    float* y = (float*)d_out;

    xprep_kernel<<<(M_DIM * (size_t)K_DIM) / (256 * 8), 256>>>(x);
    dequant_kernel<<<NGROUPS / 256, 256>>>(packed, codebook);

    const int smem_bytes = 2 * (BM + BN) * SW * (int)sizeof(unsigned);  // 73728
    cudaFuncSetAttribute(gemm_kernel, cudaFuncAttributeMaxDynamicSharedMemorySize, smem_bytes);
    dim3 grid(M_DIM / BM, N_DIM / BN);   // (16, 64), m-fastest
    gemm_kernel<<<grid, 256, smem_bytes>>>(y);
}

// round 10
// speedup vs baseline: 2.5003x; 1.1488x over previous
#include <cuda_runtime.h>
#include <cuda_fp16.h>
#include <cstdint>

// ---------------------------------------------------------------------------
// Problem dims
// ---------------------------------------------------------------------------
#define M_DIM 2048
#define N_DIM 8192
#define K_DIM 8192
#define NGROUPS ((N_DIM * K_DIM) / 8)   // 8388608

// Device-global scratch (no cudaMalloc allowed) — fp16 operands
__device__ __align__(256) __half g_w[(size_t)N_DIM * K_DIM];   // (N,K) row-major
__device__ __align__(256) __half g_x[(size_t)M_DIM * K_DIM];

// ---------------------------------------------------------------------------
// Prep: fp32 -> fp16, 8 elems/thread
// ---------------------------------------------------------------------------
__global__ void __launch_bounds__(256) xprep_kernel(const float* __restrict__ x) {
    size_t i = ((size_t)blockIdx.x * 256 + threadIdx.x) * 8;
    float4 v0 = *reinterpret_cast<const float4*>(x + i);
    float4 v1 = *reinterpret_cast<const float4*>(x + i + 4);
    union { __half2 h[4]; uint4 u; } o;
    o.h[0] = __floats2half2_rn(v0.x, v0.y);
    o.h[1] = __floats2half2_rn(v0.z, v0.w);
    o.h[2] = __floats2half2_rn(v1.x, v1.y);
    o.h[3] = __floats2half2_rn(v1.z, v1.w);
    *reinterpret_cast<uint4*>(g_x + i) = o.u;
}

// ---------------------------------------------------------------------------
// Dequant: one 3-byte group -> 8 3-bit indices -> 8 fp16 weights (16B store)
// ---------------------------------------------------------------------------
__global__ void __launch_bounds__(256) dequant_kernel(const int* __restrict__ packed,
                                                      const float* __restrict__ codebook) {
    int g = blockIdx.x * 256 + threadIdx.x;
    int p0 = packed[3 * g + 0];
    int p1 = packed[3 * g + 1];
    int p2 = packed[3 * g + 2];
    unsigned bits = (unsigned)(p0 & 255) | ((unsigned)(p1 & 255) << 8) |
                    ((unsigned)(p2 & 255) << 16);
    const float* cb = codebook + ((size_t)(g >> 4)) * 8;
    union { __half h[8]; uint4 u; } o;
#pragma unroll
    for (int j = 0; j < 8; j++)
        o.h[j] = __float2half_rn(__ldg(cb + ((bits >> (3 * j)) & 7)));
    *reinterpret_cast<uint4*>(g_w + (size_t)g * 8) = o.u;
}

// ---------------------------------------------------------------------------
// GEMM: y[m,n] = sum_k x[m,k] * w[n,k]   fp16 inputs, fp32 accumulate
// BM=BN=128, BK=64 halves, 256 threads (8 warps 2x4, warp tile 64x32)
// 3-stage cp.async ring (wait_group 1), XOR-swizzled 128B rows, ldmatrix.x4.
// ---------------------------------------------------------------------------
#define BM 128
#define BN 128
#define BKH 64                          // k-halves per stage
#define K_TILES (K_DIM / BKH)           // 128
#define STAGES 3
#define STAGE_WORDS 8192                // (128+128) rows * 32 words
#define STAGE_BYTES 32768
#define B_OFF_BYTES 16384               // B region inside a stage
#define B_OFF_WORDS 4096

__device__ __forceinline__ void cp_async16(void* s, const void* g) {
    unsigned sa = (unsigned)__cvta_generic_to_shared(s);
    asm volatile("cp.async.cg.shared.global [%0], [%1], 16;\n" ::"r"(sa), "l"(g));
}

__device__ __forceinline__ void ldsm_x4(unsigned& r0, unsigned& r1, unsigned& r2,
                                        unsigned& r3, uint32_t addr) {
    asm volatile("ldmatrix.sync.aligned.m8n8.x4.shared.b16 {%0,%1,%2,%3}, [%4];"
                 : "=r"(r0), "=r"(r1), "=r"(r2), "=r"(r3) : "r"(addr));
}

__device__ __forceinline__ void mma_f16(float* c, const unsigned* a, const unsigned* b) {
    asm volatile(
        "mma.sync.aligned.m16n8k16.row.col.f32.f16.f16.f32 "
        "{%0,%1,%2,%3}, {%4,%5,%6,%7}, {%8,%9}, {%0,%1,%2,%3};\n"
        : "+f"(c[0]), "+f"(c[1]), "+f"(c[2]), "+f"(c[3])
        : "r"(a[0]), "r"(a[1]), "r"(a[2]), "r"(a[3]), "r"(b[0]), "r"(b[1]));
}

__global__ void __launch_bounds__(256, 2) gemm_kernel(float* __restrict__ y) {
    extern __shared__ unsigned smem[];          // [STAGES][8192] b32 words
    const uint32_t smem_sa = (uint32_t)__cvta_generic_to_shared(smem);

    const int tid = threadIdx.x;
    const int wid = tid >> 5;
    const int lane = tid & 31;
    const int wm = wid >> 2;        // 0..1
    const int wn = wid & 3;         // 0..3
    const int gr = lane >> 2;       // 0..7
    const int tg = lane & 3;        // 0..3
    const int l7 = lane & 7;

    const int m0 = blockIdx.x * BM;   // m-fastest rasterization: B panels L2-resident
    const int n0 = blockIdx.y * BN;
    const __half* Ag = g_x + (size_t)m0 * K_DIM;
    const __half* Bg = g_w + (size_t)n0 * K_DIM;

    // per-lane fixed pieces of the ldmatrix addressing
    const int hiA = lane >> 4;                       // A k-half selector
    const int hiB = (lane >> 3) & 1;                 // B k-half selector
    const uint32_t a_row_b = (uint32_t)(wm * 64 + (lane & 15)) * 128;
    const uint32_t b_row_b = (uint32_t)(wn * 32 + (lane & 7) + (lane >> 4) * 8) * 128;

    float acc[4][4][4];
#pragma unroll
    for (int i = 0; i < 4; i++)
#pragma unroll
        for (int j = 0; j < 4; j++)
#pragma unroll
            for (int r = 0; r < 4; r++) acc[i][j][r] = 0.0f;

    // tile loader: 128 rows x 128B per matrix; chunk stored at (ch ^ (row&7))
    auto load_tile = [&](int kt, int st) {
        const __half* a = Ag + kt * BKH;
        const __half* b = Bg + kt * BKH;
        unsigned* sb = smem + st * STAGE_WORDS;
#pragma unroll
        for (int i = 0; i < 4; i++) {
            int f = tid + i * 256;            // 0..1023
            int row = f >> 3;
            int ch = f & 7;
            int sw = (ch ^ (row & 7)) * 4;    // swizzled word offset in row
            cp_async16(sb + row * 32 + sw, a + (size_t)row * K_DIM + ch * 8);
            cp_async16(sb + B_OFF_WORDS + row * 32 + sw, b + (size_t)row * K_DIM + ch * 8);
        }
    };

    auto compute = [&](int st) {
        const uint32_t sa = smem_sa + (uint32_t)st * STAGE_BYTES;
#pragma unroll
        for (int ks = 0; ks < 4; ks++) {       // 4 x k16 steps per BK=64
            const uint32_t swA = (uint32_t)(((2 * ks + hiA) ^ l7) << 4);
            const uint32_t swB = (uint32_t)(((2 * ks + hiB) ^ l7) << 4);
            unsigned a[4][4], b[4][2];
#pragma unroll
            for (int jp = 0; jp < 2; jp++)
                ldsm_x4(b[2 * jp][0], b[2 * jp][1], b[2 * jp + 1][0], b[2 * jp + 1][1],
                        sa + B_OFF_BYTES + b_row_b + (uint32_t)(jp * 16 * 128) + swB);
#pragma unroll
            for (int i = 0; i < 4; i++)
                ldsm_x4(a[i][0], a[i][1], a[i][2], a[i][3],
                        sa + a_row_b + (uint32_t)(i * 16 * 128) + swA);
#pragma unroll
            for (int i = 0; i < 4; i++)
#pragma unroll
                for (int j = 0; j < 4; j++) mma_f16(acc[i][j], a[i], b[j]);
        }
    };

    // ---- 3-stage pipelined mainloop (CUTLASS multistage ordering) ----
    load_tile(0, 0);
    asm volatile("cp.async.commit_group;\n");
    load_tile(1, 1);
    asm volatile("cp.async.commit_group;\n");

    int ld_st = 2, cp_st = 0;
#pragma unroll 1
    for (int kt = 0; kt < K_TILES; kt++) {
        asm volatile("cp.async.wait_group 1;\n");
        __syncthreads();                       // stage kt visible; compute(kt-1) done by all
        if (kt + 2 < K_TILES) load_tile(kt + 2, ld_st);
        asm volatile("cp.async.commit_group;\n");
        compute(cp_st);
        ld_st = (ld_st == STAGES - 1) ? 0 : ld_st + 1;
        cp_st = (cp_st == STAGES - 1) ? 0 : cp_st + 1;
    }

    // epilogue: fp32 accumulators straight to gmem
#pragma unroll
    for (int i = 0; i < 4; i++) {
#pragma unroll
        for (int j = 0; j < 4; j++) {
            int row = m0 + wm * 64 + i * 16 + gr;
            int col = n0 + wn * 32 + j * 8 + tg * 2;
            *reinterpret_cast<float2*>(y + (size_t)row * N_DIM + col) =
                make_float2(acc[i][j][0], acc[i][j][1]);
            *reinterpret_cast<float2*>(y + (size_t)(row + 8) * N_DIM + col) =
                make_float2(acc[i][j][2], acc[i][j][3]);
        }
    }
}

// ---------------------------------------------------------------------------
// Launch
// ---------------------------------------------------------------------------
extern "C" void kernel_launch(void* const* d_in, const int* in_sizes, int n_in,
                              void* d_out, int out_size) {
    const float* x = nullptr;
    const int* packed = nullptr;
    const float* codebook = nullptr;
    for (int i = 0; i < n_in; i++) {
        if (in_sizes[i] == M_DIM * K_DIM) x = (const float*)d_in[i];
        else if (in_sizes[i] == NGROUPS * 3) packed = (const int*)d_in[i];
        else codebook = (const float*)d_in[i];
    }
    float* y = (float*)d_out;

    xprep_kernel<<<(M_DIM * (size_t)K_DIM) / (256 * 8), 256>>>(x);
    dequant_kernel<<<NGROUPS / 256, 256>>>(packed, codebook);

    const int smem_bytes = STAGES * STAGE_BYTES;   // 98304
    cudaFuncSetAttribute(gemm_kernel, cudaFuncAttributeMaxDynamicSharedMemorySize, smem_bytes);
    dim3 grid(M_DIM / BM, N_DIM / BN);   // (16, 64), m-fastest
    gemm_kernel<<<grid, 256, smem_bytes>>>(y);
}